// round 6
// baseline (speedup 1.0000x reference)
#include <cuda_runtime.h>
#include <cuda_bf16.h>
#include <math.h>
#include <stdint.h>

#define BB    32
#define CINC  128
#define HH    64
#define WW    64
#define COUTC 128
#define NK    4
#define HIDN  32
#define TEMPF 34.0f

// halo-padded channel-last input: [B][66][66][CIN] bf16 (hi and lo split)
#define HP 66
__device__ __nv_bfloat16 g_xh[(size_t)BB*HP*HP*CINC];
__device__ __nv_bfloat16 g_xl[(size_t)BB*HP*HP*CINC];
// aggregated split weights: [B][9][COUT][CIN] bf16
__device__ __nv_bfloat16 g_wh[(size_t)BB*9*COUTC*CINC];
__device__ __nv_bfloat16 g_wl[(size_t)BB*9*COUTC*CINC];
__device__ float g_ctx[BB*CINC];
__device__ float g_att[BB*NK];
__device__ float g_aggb[BB*COUTC];

// ---------------- PTX helpers ----------------
__device__ __forceinline__ uint32_t smem_u32(const void* p) {
    uint32_t a;
    asm("{ .reg .u64 t; cvta.to.shared.u64 t, %1; cvt.u32.u64 %0, t; }" : "=r"(a) : "l"(p));
    return a;
}
#define SW128(off) ((off) ^ (((off) >> 3) & 0x70))

__device__ __forceinline__ void cp16(uint32_t dst, const void* src) {
    asm volatile("cp.async.cg.shared.global [%0], [%1], 16;" :: "r"(dst), "l"(src));
}
#define CP_COMMIT() asm volatile("cp.async.commit_group;" ::: "memory")
#define CP_WAIT1()  asm volatile("cp.async.wait_group 1;" ::: "memory")
#define CP_WAIT0()  asm volatile("cp.async.wait_group 0;" ::: "memory")

__device__ __forceinline__ void ldmx4(uint32_t* r, uint32_t addr) {
    asm volatile("ldmatrix.sync.aligned.m8n8.x4.shared.b16 {%0,%1,%2,%3}, [%4];"
                 : "=r"(r[0]), "=r"(r[1]), "=r"(r[2]), "=r"(r[3]) : "r"(addr));
}
__device__ __forceinline__ void mma_bf16(float* d, const uint32_t* a, const uint32_t* b) {
    asm volatile("mma.sync.aligned.m16n8k16.row.col.f32.bf16.bf16.f32 "
                 "{%0,%1,%2,%3}, {%4,%5,%6,%7}, {%8,%9}, {%0,%1,%2,%3};"
                 : "+f"(d[0]), "+f"(d[1]), "+f"(d[2]), "+f"(d[3])
                 : "r"(a[0]), "r"(a[1]), "r"(a[2]), "r"(a[3]), "r"(b[0]), "r"(b[1]));
}

// ---------------- Kernel 1: global average pool ----------------
__global__ void mean_kernel(const float* __restrict__ x) {
    int bc = blockIdx.x;
    const float4* p = (const float4*)(x + (size_t)bc * (HH*WW));
    float s = 0.f;
    #pragma unroll
    for (int i = 0; i < 4; ++i) {
        float4 v = p[threadIdx.x + i*256];
        s += v.x + v.y + v.z + v.w;
    }
    #pragma unroll
    for (int o = 16; o > 0; o >>= 1) s += __shfl_xor_sync(0xffffffffu, s, o);
    __shared__ float red[8];
    if ((threadIdx.x & 31) == 0) red[threadIdx.x >> 5] = s;
    __syncthreads();
    if (threadIdx.x < 8) {
        s = red[threadIdx.x];
        #pragma unroll
        for (int o = 4; o > 0; o >>= 1) s += __shfl_xor_sync(0xffu, s, o);
        if (threadIdx.x == 0) g_ctx[bc] = s * (1.0f / (HH*WW));
    }
}

// ---------------- Kernel 2: attention MLP + softmax + agg bias ----------------
__global__ void __launch_bounds__(128) att_kernel(const float* __restrict__ fc1_w,
                                                  const float* __restrict__ fc2_w,
                                                  const float* __restrict__ fc2_b,
                                                  const float* __restrict__ bias) {
    const int b = blockIdx.x;
    const int tid = threadIdx.x, wid = tid >> 5, lane = tid & 31;
    __shared__ float s_ctx[CINC];
    __shared__ float s_hid[HIDN];
    __shared__ float s_att[NK];

    s_ctx[tid] = g_ctx[b*CINC + tid];
    __syncthreads();

    #pragma unroll
    for (int i = 0; i < 8; ++i) {
        int h = wid*8 + i;
        float s = 0.f;
        #pragma unroll
        for (int j = 0; j < 4; ++j) {
            int c = lane + j*32;
            s += s_ctx[c] * fc1_w[h*CINC + c];
        }
        #pragma unroll
        for (int o = 16; o > 0; o >>= 1) s += __shfl_xor_sync(0xffffffffu, s, o);
        if (lane == 0) s_hid[h] = fmaxf(s, 0.f);
    }
    __syncthreads();

    if (wid == 0) {
        int k = lane >> 3, l8 = lane & 7;
        float s = 0.f;
        #pragma unroll
        for (int j = 0; j < 4; ++j) {
            int h = l8 + j*8;
            s += s_hid[h] * fc2_w[k*HIDN + h];
        }
        #pragma unroll
        for (int o = 4; o > 0; o >>= 1) s += __shfl_xor_sync(0xffffffffu, s, o);
        s += fc2_b[k];
        float lg = s * (1.0f / TEMPF);
        float m = lg;
        #pragma unroll
        for (int o = 16; o >= 8; o >>= 1) m = fmaxf(m, __shfl_xor_sync(0xffffffffu, m, o));
        float e = expf(lg - m);
        float sum = e;
        #pragma unroll
        for (int o = 16; o >= 8; o >>= 1) sum += __shfl_xor_sync(0xffffffffu, sum, o);
        if (l8 == 0) {
            float a = e / sum;
            s_att[k] = a;
            g_att[b*NK + k] = a;
        }
    }
    __syncthreads();

    float sb = 0.f;
    #pragma unroll
    for (int k = 0; k < NK; ++k) sb += s_att[k] * bias[k*COUTC + tid];
    g_aggb[b*COUTC + tid] = sb;
}

// ---------------- Kernel 3: zero halo borders ----------------
__global__ void halo_kernel() {
    int b = blockIdx.y, yy = blockIdx.x;
    bool full = (yy == 0 || yy == HP-1);
    int nsite = full ? HP : 2;
    for (int i = threadIdx.x; i < nsite*CINC; i += 256) {
        int si = i >> 7, ci = i & 127;
        int xx = full ? si : (si ? HP-1 : 0);
        size_t off = (((size_t)b*HP + yy)*HP + xx)*CINC + ci;
        g_xh[off] = __float2bfloat16(0.f);
        g_xl[off] = __float2bfloat16(0.f);
    }
}

// ---------------- Kernel 4: transpose+split x ----------------
__global__ void __launch_bounds__(256) prepx_kernel(const float* __restrict__ x) {
    __shared__ float tile[CINC][33];
    int x0 = blockIdx.x * 32, y = blockIdx.y, b = blockIdx.z;
    int tid = threadIdx.x;
    #pragma unroll
    for (int r = 0; r < 16; ++r) {
        int ci = r*8 + (tid >> 5), xp = tid & 31;
        tile[ci][xp] = x[(((size_t)b*CINC + ci)*HH + y)*WW + x0 + xp];
    }
    __syncthreads();
    int ci = tid & 127;
    #pragma unroll
    for (int r = 0; r < 16; ++r) {
        int xp = r*2 + (tid >> 7);
        float v = tile[ci][xp];
        __nv_bfloat16 hi = __float2bfloat16(v);
        __nv_bfloat16 lo = __float2bfloat16(v - __bfloat162float(hi));
        size_t off = (((size_t)b*HP + (y+1))*HP + (x0 + xp + 1))*CINC + ci;
        g_xh[off] = hi;
        g_xl[off] = lo;
    }
}

// ---------------- Kernel 5: aggregate + split weights ----------------
__global__ void __launch_bounds__(256) prepw_kernel(const float* __restrict__ weight) {
    int co = blockIdx.x, b = blockIdx.y;
    float a[NK];
    #pragma unroll
    for (int k = 0; k < NK; ++k) a[k] = g_att[b*NK + k];
    for (int idx = threadIdx.x; idx < 9*CINC; idx += 256) {
        int t = idx >> 7, ci = idx & 127;
        float s = 0.f;
        #pragma unroll
        for (int k = 0; k < NK; ++k)
            s += a[k] * weight[((size_t)(k*COUTC + co)*CINC + ci)*9 + t];
        __nv_bfloat16 hi = __float2bfloat16(s);
        __nv_bfloat16 lo = __float2bfloat16(s - __bfloat162float(hi));
        size_t off = (((size_t)(b*9 + t)*COUTC) + co)*CINC + ci;
        g_wh[off] = hi;
        g_wl[off] = lo;
    }
}

// ---------------- Kernel 6: HMMA bf16-split conv GEMM ----------------
// CTA: M=256 pixels (4 rows x 64), N=128 couts. 18 stages of K=64 (tap x ci-half).
// Stage = Ah(32K) Al(32K) Bh(16K) Bl(16K) = 96KB, double-buffered.
#define A_BYTES 32768
#define B_BYTES 16384
#define STAGE_B (2*A_BYTES + 2*B_BYTES)     // 98304
#define SMEM_TOTAL (2*STAGE_B)              // 196608

__global__ void __launch_bounds__(256, 1) conv_kernel(float* __restrict__ out) {
    extern __shared__ __align__(1024) char smem[];
    const uint32_t sbase = smem_u32(smem);
    const int tid = threadIdx.x, wid = tid >> 5, lane = tid & 31;
    const int b = blockIdx.y;
    const int y0 = blockIdx.x * 4;

    const int warp_m = wid >> 1;          // 0..3 : pixel rows 64*warp_m
    const int warp_n = wid & 1;           // 0..1 : couts 64*warp_n

    const int quad = lane >> 3, l7 = lane & 7;
    const int a_row_off = ((quad & 1) << 3) + l7;
    const int a_k_off   = (quad >> 1) << 4;
    const int b_row_off = ((quad >> 1) << 3) + l7;
    const int b_k_off   = (quad & 1) << 4;

    float acc[4][8][4];
    #pragma unroll
    for (int mi = 0; mi < 4; ++mi)
        #pragma unroll
        for (int nf = 0; nf < 8; ++nf)
            #pragma unroll
            for (int e = 0; e < 4; ++e) acc[mi][nf][e] = 0.f;

    // ---- stage issue: 6144 x 16B cp.async across 256 threads (24 each)
    auto issue_stage = [&](int buf, int g) {
        const int tap = g >> 1, c2 = g & 1;
        const int dy = tap / 3, dx = tap % 3;
        const uint32_t sb = sbase + buf * STAGE_B;
        // A: idx 0..4095  (split, 256 rows, 8 chunks)
        #pragma unroll
        for (int i = 0; i < 16; ++i) {
            int idx = tid + i*256;
            int sp  = idx >> 11;            // 0=hi 1=lo
            int r   = (idx >> 3) & 255;
            int c8  = idx & 7;
            int pr = r >> 6, pc = r & 63;
            size_t e = (((size_t)b*HP + (y0 + pr + dy))*HP + (pc + dx))*CINC + c2*64;
            const char* src = (const char*)(sp ? g_xl : g_xh) + e*2 + c8*16;
            uint32_t dst = sb + sp*A_BYTES + SW128(r*128 + c8*16);
            cp16(dst, src);
        }
        // B: idx 0..2047 (split, 128 rows, 8 chunks)
        #pragma unroll
        for (int i = 0; i < 8; ++i) {
            int idx = tid + i*256;
            int sp  = idx >> 10;
            int r   = (idx >> 3) & 127;
            int c8  = idx & 7;
            size_t e = (((size_t)(b*9 + tap))*COUTC + r)*CINC + c2*64;
            const char* src = (const char*)(sp ? g_wl : g_wh) + e*2 + c8*16;
            uint32_t dst = sb + 2*A_BYTES + sp*B_BYTES + SW128(r*128 + c8*16);
            cp16(dst, src);
        }
    };

    issue_stage(0, 0);
    CP_COMMIT();

    for (int g = 0; g < 18; ++g) {
        __syncthreads();
        if (g + 1 < 18) {
            issue_stage((g + 1) & 1, g + 1);
            CP_COMMIT();
            CP_WAIT1();
        } else {
            CP_WAIT0();
        }
        __syncthreads();

        const uint32_t sb = sbase + (g & 1) * STAGE_B;
        const uint32_t ah_b = sb;
        const uint32_t al_b = sb + A_BYTES;
        const uint32_t bh_b = sb + 2*A_BYTES;
        const uint32_t bl_b = sb + 2*A_BYTES + B_BYTES;

        #pragma unroll
        for (int kc = 0; kc < 4; ++kc) {
            const int kb = kc * 32;
            uint32_t Bh[4][4], Bl[4][4];
            #pragma unroll
            for (int nj = 0; nj < 4; ++nj) {
                int row = warp_n*64 + nj*16 + b_row_off;
                uint32_t off = SW128(row*128 + kb + b_k_off);
                ldmx4(Bh[nj], bh_b + off);
                ldmx4(Bl[nj], bl_b + off);
            }
            #pragma unroll
            for (int mi = 0; mi < 4; ++mi) {
                uint32_t Ah[4], Al[4];
                int row = warp_m*64 + mi*16 + a_row_off;
                uint32_t off = SW128(row*128 + kb + a_k_off);
                ldmx4(Ah, ah_b + off);
                ldmx4(Al, al_b + off);
                #pragma unroll
                for (int nf = 0; nf < 8; ++nf) {
                    const uint32_t* bh = &Bh[nf >> 1][(nf & 1) * 2];
                    const uint32_t* bl = &Bl[nf >> 1][(nf & 1) * 2];
                    mma_bf16(acc[mi][nf], Ah, bh);   // hh
                    mma_bf16(acc[mi][nf], Al, bh);   // lh
                    mma_bf16(acc[mi][nf], Ah, bl);   // hl
                }
            }
        }
    }

    // ---- epilogue: regs -> smem [co][p] (pitch 260) -> float4 coalesced stores
    __syncthreads();
    float* stage = (float*)smem;            // [128][260]
    #pragma unroll
    for (int mi = 0; mi < 4; ++mi)
        #pragma unroll
        for (int nf = 0; nf < 8; ++nf)
            #pragma unroll
            for (int e = 0; e < 4; ++e) {
                int p  = warp_m*64 + mi*16 + (lane >> 2) + ((e >> 1) << 3);
                int co = warp_n*64 + nf*8 + ((lane & 3) << 1) + (e & 1);
                stage[co*260 + p] = acc[mi][nf][e];
            }
    __syncthreads();
    #pragma unroll
    for (int i = 0; i < 32; ++i) {
        int idx = tid + i*256;               // 8192 quads
        int co = idx >> 6, pq = idx & 63;
        int p = pq * 4;
        float bb = g_aggb[b*COUTC + co];
        const float* sp = stage + co*260 + p;
        float4 v;
        v.x = sp[0] + bb; v.y = sp[1] + bb; v.z = sp[2] + bb; v.w = sp[3] + bb;
        *(float4*)(out + (((size_t)b*COUTC + co)*HH + y0 + (p >> 6))*WW + (p & 63)) = v;
    }
}

extern "C" void kernel_launch(void* const* d_in, const int* in_sizes, int n_in,
                              void* d_out, int out_size) {
    const float* x      = (const float*)d_in[0];
    const float* fc1_w  = (const float*)d_in[1];
    const float* fc2_w  = (const float*)d_in[2];
    const float* fc2_b  = (const float*)d_in[3];
    const float* weight = (const float*)d_in[4];
    const float* bias   = (const float*)d_in[5];
    float* out = (float*)d_out;

    cudaFuncSetAttribute(conv_kernel,
                         cudaFuncAttributeMaxDynamicSharedMemorySize, SMEM_TOTAL);

    mean_kernel<<<BB*CINC, 256>>>(x);
    att_kernel<<<BB, 128>>>(fc1_w, fc2_w, fc2_b, bias);
    halo_kernel<<<dim3(HP, BB), 256>>>();
    prepx_kernel<<<dim3(2, HH, BB), 256>>>(x);
    prepw_kernel<<<dim3(COUTC, BB), 256>>>(weight);
    conv_kernel<<<dim3(HH/4, BB), 256, SMEM_TOTAL>>>(out);
}

// round 7
// speedup vs baseline: 1.1018x; 1.1018x over previous
#include <cuda_runtime.h>
#include <cuda_bf16.h>
#include <math.h>
#include <stdint.h>

#define BB    32
#define CINC  128
#define HH    64
#define WW    64
#define COUTC 128
#define NK    4
#define HIDN  32
#define TEMPF 34.0f

// halo-padded channel-last input: [B][66][66][CIN] bf16 (hi and lo split)
#define HP 66
__device__ __nv_bfloat16 g_xh[(size_t)BB*HP*HP*CINC];
__device__ __nv_bfloat16 g_xl[(size_t)BB*HP*HP*CINC];
// aggregated split weights: [B][9][COUT][CIN] bf16
__device__ __nv_bfloat16 g_wh[(size_t)BB*9*COUTC*CINC];
__device__ __nv_bfloat16 g_wl[(size_t)BB*9*COUTC*CINC];
__device__ float g_part[(size_t)BB*CINC*128];   // mean partials: [b][ci][y*2+xhalf]
__device__ float g_att[BB*NK];
__device__ float g_aggb[BB*COUTC];

// ---------------- PTX helpers ----------------
__device__ __forceinline__ uint32_t smem_u32(const void* p) {
    uint32_t a;
    asm("{ .reg .u64 t; cvta.to.shared.u64 t, %1; cvt.u32.u64 %0, t; }" : "=r"(a) : "l"(p));
    return a;
}
#define SW128(off) ((off) ^ (((off) >> 3) & 0x70))

__device__ __forceinline__ void cp16(uint32_t dst, const void* src) {
    asm volatile("cp.async.cg.shared.global [%0], [%1], 16;" :: "r"(dst), "l"(src));
}
#define CP_COMMIT() asm volatile("cp.async.commit_group;" ::: "memory")
#define CP_WAIT1()  asm volatile("cp.async.wait_group 1;" ::: "memory")
#define CP_WAIT0()  asm volatile("cp.async.wait_group 0;" ::: "memory")

__device__ __forceinline__ void ldmx4(uint32_t* r, uint32_t addr) {
    asm volatile("ldmatrix.sync.aligned.m8n8.x4.shared.b16 {%0,%1,%2,%3}, [%4];"
                 : "=r"(r[0]), "=r"(r[1]), "=r"(r[2]), "=r"(r[3]) : "r"(addr));
}
__device__ __forceinline__ void mma_bf16(float* d, const uint32_t* a, const uint32_t* b) {
    asm volatile("mma.sync.aligned.m16n8k16.row.col.f32.bf16.bf16.f32 "
                 "{%0,%1,%2,%3}, {%4,%5,%6,%7}, {%8,%9}, {%0,%1,%2,%3};"
                 : "+f"(d[0]), "+f"(d[1]), "+f"(d[2]), "+f"(d[3])
                 : "r"(a[0]), "r"(a[1]), "r"(a[2]), "r"(a[3]), "r"(b[0]), "r"(b[1]));
}

// ---------------- Kernel 1: zero halo borders ----------------
__global__ void halo_kernel() {
    int b = blockIdx.y, yy = blockIdx.x;
    bool full = (yy == 0 || yy == HP-1);
    int nsite = full ? HP : 2;
    for (int i = threadIdx.x; i < nsite*CINC; i += 256) {
        int si = i >> 7, ci = i & 127;
        int xx = full ? si : (si ? HP-1 : 0);
        size_t off = (((size_t)b*HP + yy)*HP + xx)*CINC + ci;
        g_xh[off] = __float2bfloat16(0.f);
        g_xl[off] = __float2bfloat16(0.f);
    }
}

// ---------------- Kernel 2: transpose+split x, fused mean partials ----------------
__global__ void __launch_bounds__(256) prepx_kernel(const float* __restrict__ x) {
    __shared__ float tile[CINC][33];
    __shared__ float s_red[256];
    int x0 = blockIdx.x * 32, y = blockIdx.y, b = blockIdx.z;
    int tid = threadIdx.x;
    #pragma unroll
    for (int r = 0; r < 16; ++r) {
        int ci = r*8 + (tid >> 5), xp = tid & 31;
        tile[ci][xp] = x[(((size_t)b*CINC + ci)*HH + y)*WW + x0 + xp];
    }
    __syncthreads();
    int ci = tid & 127;
    float s = 0.f;
    #pragma unroll
    for (int r = 0; r < 16; ++r) {
        int xp = r*2 + (tid >> 7);
        float v = tile[ci][xp];
        s += v;
        __nv_bfloat16 hi = __float2bfloat16(v);
        __nv_bfloat16 lo = __float2bfloat16(v - __bfloat162float(hi));
        size_t off = (((size_t)b*HP + (y+1))*HP + (x0 + xp + 1))*CINC + ci;
        g_xh[off] = hi;
        g_xl[off] = lo;
    }
    s_red[tid] = s;
    __syncthreads();
    if (tid < 128)
        g_part[((size_t)b*CINC + tid)*128 + y*2 + blockIdx.x] = s_red[tid] + s_red[tid + 128];
}

// ---------------- Kernel 3: attention MLP + softmax + agg bias ----------------
__global__ void __launch_bounds__(128) att_kernel(const float* __restrict__ fc1_w,
                                                  const float* __restrict__ fc2_w,
                                                  const float* __restrict__ fc2_b,
                                                  const float* __restrict__ bias) {
    const int b = blockIdx.x;
    const int tid = threadIdx.x, wid = tid >> 5, lane = tid & 31;
    __shared__ float s_ctx[CINC];
    __shared__ float s_hid[HIDN];
    __shared__ float s_att[NK];

    {   // reduce mean partials: thread tid = ci
        const float* pp = g_part + ((size_t)b*CINC + tid)*128;
        float s = 0.f;
        #pragma unroll 8
        for (int j = 0; j < 128; ++j) s += pp[j];
        s_ctx[tid] = s * (1.0f / (HH*WW));
    }
    __syncthreads();

    #pragma unroll
    for (int i = 0; i < 8; ++i) {
        int h = wid*8 + i;
        float s = 0.f;
        #pragma unroll
        for (int j = 0; j < 4; ++j) {
            int c = lane + j*32;
            s += s_ctx[c] * fc1_w[h*CINC + c];
        }
        #pragma unroll
        for (int o = 16; o > 0; o >>= 1) s += __shfl_xor_sync(0xffffffffu, s, o);
        if (lane == 0) s_hid[h] = fmaxf(s, 0.f);
    }
    __syncthreads();

    if (wid == 0) {
        int k = lane >> 3, l8 = lane & 7;
        float s = 0.f;
        #pragma unroll
        for (int j = 0; j < 4; ++j) {
            int h = l8 + j*8;
            s += s_hid[h] * fc2_w[k*HIDN + h];
        }
        #pragma unroll
        for (int o = 4; o > 0; o >>= 1) s += __shfl_xor_sync(0xffffffffu, s, o);
        s += fc2_b[k];
        float lg = s * (1.0f / TEMPF);
        float m = lg;
        #pragma unroll
        for (int o = 16; o >= 8; o >>= 1) m = fmaxf(m, __shfl_xor_sync(0xffffffffu, m, o));
        float e = expf(lg - m);
        float sum = e;
        #pragma unroll
        for (int o = 16; o >= 8; o >>= 1) sum += __shfl_xor_sync(0xffffffffu, sum, o);
        if (l8 == 0) {
            float a = e / sum;
            s_att[k] = a;
            g_att[b*NK + k] = a;
        }
    }
    __syncthreads();

    float sb = 0.f;
    #pragma unroll
    for (int k = 0; k < NK; ++k) sb += s_att[k] * bias[k*COUTC + tid];
    g_aggb[b*COUTC + tid] = sb;
}

// ---------------- Kernel 4: aggregate + split weights ----------------
__global__ void __launch_bounds__(256) prepw_kernel(const float* __restrict__ weight) {
    int co = blockIdx.x, b = blockIdx.y;
    float a[NK];
    #pragma unroll
    for (int k = 0; k < NK; ++k) a[k] = g_att[b*NK + k];
    for (int idx = threadIdx.x; idx < 9*CINC; idx += 256) {
        int t = idx >> 7, ci = idx & 127;
        float s = 0.f;
        #pragma unroll
        for (int k = 0; k < NK; ++k)
            s += a[k] * weight[((size_t)(k*COUTC + co)*CINC + ci)*9 + t];
        __nv_bfloat16 hi = __float2bfloat16(s);
        __nv_bfloat16 lo = __float2bfloat16(s - __bfloat162float(hi));
        size_t off = (((size_t)(b*9 + t)*COUTC) + co)*CINC + ci;
        g_wh[off] = hi;
        g_wl[off] = lo;
    }
}

// ---------------- Kernel 5: HMMA bf16-split conv GEMM, A-resident ----------------
// CTA: M=128 pixels (2 rows x 64), N=128 couts.
// A: padded input window 4 rows x 66 cols x 64ci x {hi,lo} = 67584 B, one buffer
//    per ci-half (staged twice). All 9 taps read shifted views of it.
// B: 32KB per (tap, ci-half), double-buffered.
#define A_LINES 264                    // 4*66 lines of 128B
#define A_SP    (A_LINES*128)          // 33792 per split
#define A_BUF   (2*A_SP)               // 67584
#define B_SP    16384
#define B_BUF   (2*B_SP)               // 32768
#define B_OFF   (2*A_BUF)              // 135168
#define SMEM_TOTAL (B_OFF + 2*B_BUF)   // 200704

__global__ void __launch_bounds__(256, 1) conv_kernel(float* __restrict__ out) {
    extern __shared__ __align__(1024) char smem[];
    const uint32_t sbase = smem_u32(smem);
    const int tid = threadIdx.x, wid = tid >> 5, lane = tid & 31;
    const int b = blockIdx.y;
    const int y0 = blockIdx.x * 2;

    const int warp_m = wid >> 1;          // 0..3 : pixel rows 32*warp_m
    const int warp_n = wid & 1;           // 0..1 : couts 64*warp_n

    const int quad = lane >> 3, l7 = lane & 7;
    const int a_row_off = ((quad & 1) << 3) + l7;
    const int a_k_off   = (quad >> 1) << 4;
    const int b_row_off = ((quad >> 1) << 3) + l7;
    const int b_k_off   = (quad & 1) << 4;

    float acc[2][8][4];
    #pragma unroll
    for (int mi = 0; mi < 2; ++mi)
        #pragma unroll
        for (int nf = 0; nf < 8; ++nf)
            #pragma unroll
            for (int e = 0; e < 4; ++e) acc[mi][nf][e] = 0.f;

    // ---- stage A window for ci-half c2 into A buffer abuf (4224 cp16)
    auto issue_A = [&](int abuf, int c2) {
        for (int idx = tid; idx < 2*A_LINES*8; idx += 256) {
            int sp   = idx >= A_LINES*8;
            int rem  = idx - sp*(A_LINES*8);
            int line = rem >> 3;
            int c8   = rem & 7;
            int r4   = line / 66;
            int c66  = line - r4*66;
            size_t e = (((size_t)b*HP + y0 + r4)*HP + c66)*CINC + c2*64;
            const char* src = (const char*)(sp ? g_xl : g_xh) + e*2 + c8*16;
            uint32_t dst = sbase + abuf*A_BUF + sp*A_SP + line*128
                         + ((c8*16) ^ ((line & 7) << 4));
            cp16(dst, src);
        }
    };
    // ---- stage B tile for (tap, ci-half) into B buffer bbuf (2048 cp16)
    auto issue_B = [&](int bbuf, int g) {
        const int tap = g % 9, c2 = g / 9;
        #pragma unroll
        for (int i = 0; i < 8; ++i) {
            int idx = tid + i*256;
            int sp  = idx >> 10;
            int r   = (idx >> 3) & 127;
            int c8  = idx & 7;
            size_t e = (((size_t)(b*9 + tap))*COUTC + r)*CINC + c2*64;
            const char* src = (const char*)(sp ? g_wl : g_wh) + e*2 + c8*16;
            uint32_t dst = sbase + B_OFF + bbuf*B_BUF + sp*B_SP + SW128(r*128 + c8*16);
            cp16(dst, src);
        }
    };

    issue_A(0, 0);
    CP_COMMIT();
    issue_B(0, 0);
    CP_COMMIT();

    for (int g = 0; g < 18; ++g) {
        __syncthreads();                      // prior compute done before buffer reuse
        if (g + 1 < 18) {
            issue_B((g + 1) & 1, g + 1);
            if (g + 1 == 6) issue_A(1, 1);    // prefetch second-half A, merged group
            CP_COMMIT();
            CP_WAIT1();
        } else {
            CP_WAIT0();
        }
        __syncthreads();

        const int tap = g % 9;
        const int dy = tap / 3, dx = tap % 3;
        const uint32_t a_h = sbase + (g < 9 ? 0 : 1) * A_BUF;
        const uint32_t a_l = a_h + A_SP;
        const uint32_t b_h = sbase + B_OFF + (g & 1) * B_BUF;
        const uint32_t b_l = b_h + B_SP;

        #pragma unroll
        for (int kc = 0; kc < 4; ++kc) {
            const int kb = kc * 32;
            uint32_t Ah[2][4], Al[2][4], Bh[4][4], Bl[4][4];
            #pragma unroll
            for (int mi = 0; mi < 2; ++mi) {
                int p = warp_m*32 + mi*16 + a_row_off;
                int line = ((p >> 6) + dy)*66 + (p & 63) + dx;
                uint32_t off = line*128 + ((kb + a_k_off) ^ ((line & 7) << 4));
                ldmx4(Ah[mi], a_h + off);
                ldmx4(Al[mi], a_l + off);
            }
            #pragma unroll
            for (int nj = 0; nj < 4; ++nj) {
                int row = warp_n*64 + nj*16 + b_row_off;
                uint32_t off = SW128(row*128 + kb + b_k_off);
                ldmx4(Bh[nj], b_h + off);
                ldmx4(Bl[nj], b_l + off);
            }
            #pragma unroll
            for (int mi = 0; mi < 2; ++mi)
                #pragma unroll
                for (int nf = 0; nf < 8; ++nf) {
                    const uint32_t* bh = &Bh[nf >> 1][(nf & 1) * 2];
                    const uint32_t* bl = &Bl[nf >> 1][(nf & 1) * 2];
                    mma_bf16(acc[mi][nf], Ah[mi], bh);   // hh
                    mma_bf16(acc[mi][nf], Al[mi], bh);   // lh
                    mma_bf16(acc[mi][nf], Ah[mi], bl);   // hl
                }
        }
    }

    // ---- epilogue: regs -> smem [co][p] -> coalesced gmem + bias (overlays Abuf0)
    __syncthreads();
    float* stage = (float*)smem;            // [128][132] = 67584 B
    #pragma unroll
    for (int mi = 0; mi < 2; ++mi)
        #pragma unroll
        for (int nf = 0; nf < 8; ++nf)
            #pragma unroll
            for (int e = 0; e < 4; ++e) {
                int p  = warp_m*32 + mi*16 + (lane >> 2) + ((e >> 1) << 3);
                int co = warp_n*64 + nf*8 + ((lane & 3) << 1) + (e & 1);
                stage[co*132 + p] = acc[mi][nf][e];
            }
    __syncthreads();
    #pragma unroll
    for (int i = 0; i < 16; ++i) {
        int idx = tid + i*256;               // 4096 quads
        int co = idx >> 5, pq = idx & 31;
        int p = pq * 4;
        float bb = g_aggb[b*COUTC + co];
        const float* sp = stage + co*132 + p;
        float4 v;
        v.x = sp[0] + bb; v.y = sp[1] + bb; v.z = sp[2] + bb; v.w = sp[3] + bb;
        *(float4*)(out + (((size_t)b*COUTC + co)*HH + y0 + (p >> 6))*WW + (p & 63)) = v;
    }
}

extern "C" void kernel_launch(void* const* d_in, const int* in_sizes, int n_in,
                              void* d_out, int out_size) {
    const float* x      = (const float*)d_in[0];
    const float* fc1_w  = (const float*)d_in[1];
    const float* fc2_w  = (const float*)d_in[2];
    const float* fc2_b  = (const float*)d_in[3];
    const float* weight = (const float*)d_in[4];
    const float* bias   = (const float*)d_in[5];
    float* out = (float*)d_out;

    cudaFuncSetAttribute(conv_kernel,
                         cudaFuncAttributeMaxDynamicSharedMemorySize, SMEM_TOTAL);

    halo_kernel<<<dim3(HP, BB), 256>>>();
    prepx_kernel<<<dim3(2, HH, BB), 256>>>(x);
    att_kernel<<<BB, 128>>>(fc1_w, fc2_w, fc2_b, bias);
    prepw_kernel<<<dim3(COUTC, BB), 256>>>(weight);
    conv_kernel<<<dim3(HH/2, BB), 256, SMEM_TOTAL>>>(out);
}

// round 8
// speedup vs baseline: 1.1492x; 1.0431x over previous
#include <cuda_runtime.h>
#include <cuda_bf16.h>
#include <math.h>
#include <stdint.h>

#define BB    32
#define CINC  128
#define HH    64
#define WW    64
#define COUTC 128
#define NK    4
#define HIDN  32
#define TEMPF 34.0f

// halo-padded channel-last input: [B][66][66][CIN] bf16 (hi and lo split)
#define HP 66
__device__ __nv_bfloat16 g_xh[(size_t)BB*HP*HP*CINC];
__device__ __nv_bfloat16 g_xl[(size_t)BB*HP*HP*CINC];
// aggregated split weights: [B][9][COUT][CIN] bf16
__device__ __nv_bfloat16 g_wh[(size_t)BB*9*COUTC*CINC];
__device__ __nv_bfloat16 g_wl[(size_t)BB*9*COUTC*CINC];
__device__ float g_part[(size_t)BB*CINC*128];   // mean partials: [b][ci][y*2+xhalf]
__device__ float g_att[BB*NK];
__device__ float g_aggb[BB*COUTC];

// ---------------- PTX helpers ----------------
__device__ __forceinline__ uint32_t smem_u32(const void* p) {
    uint32_t a;
    asm("{ .reg .u64 t; cvta.to.shared.u64 t, %1; cvt.u32.u64 %0, t; }" : "=r"(a) : "l"(p));
    return a;
}
#define SW128(off) ((off) ^ (((off) >> 3) & 0x70))

__device__ __forceinline__ void cp16(uint32_t dst, const void* src) {
    asm volatile("cp.async.cg.shared.global [%0], [%1], 16;" :: "r"(dst), "l"(src));
}
#define CP_COMMIT() asm volatile("cp.async.commit_group;" ::: "memory")
#define CP_WAIT1()  asm volatile("cp.async.wait_group 1;" ::: "memory")
#define CP_WAIT0()  asm volatile("cp.async.wait_group 0;" ::: "memory")

__device__ __forceinline__ void ldmx4(uint32_t* r, uint32_t addr) {
    asm volatile("ldmatrix.sync.aligned.m8n8.x4.shared.b16 {%0,%1,%2,%3}, [%4];"
                 : "=r"(r[0]), "=r"(r[1]), "=r"(r[2]), "=r"(r[3]) : "r"(addr));
}
__device__ __forceinline__ void mma_bf16(float* d, const uint32_t* a, const uint32_t* b) {
    asm volatile("mma.sync.aligned.m16n8k16.row.col.f32.bf16.bf16.f32 "
                 "{%0,%1,%2,%3}, {%4,%5,%6,%7}, {%8,%9}, {%0,%1,%2,%3};"
                 : "+f"(d[0]), "+f"(d[1]), "+f"(d[2]), "+f"(d[3])
                 : "r"(a[0]), "r"(a[1]), "r"(a[2]), "r"(a[3]), "r"(b[0]), "r"(b[1]));
}

// ---------------- Kernel 1: zero halo borders ----------------
__global__ void halo_kernel() {
    int b = blockIdx.y, yy = blockIdx.x;
    bool full = (yy == 0 || yy == HP-1);
    int nsite = full ? HP : 2;
    for (int i = threadIdx.x; i < nsite*CINC; i += 256) {
        int si = i >> 7, ci = i & 127;
        int xx = full ? si : (si ? HP-1 : 0);
        size_t off = (((size_t)b*HP + yy)*HP + xx)*CINC + ci;
        g_xh[off] = __float2bfloat16(0.f);
        g_xl[off] = __float2bfloat16(0.f);
    }
}

// ---------------- Kernel 2: transpose+split x, fused mean partials ----------------
__global__ void __launch_bounds__(256) prepx_kernel(const float* __restrict__ x) {
    __shared__ float tile[CINC][33];
    __shared__ float s_red[256];
    int x0 = blockIdx.x * 32, y = blockIdx.y, b = blockIdx.z;
    int tid = threadIdx.x;
    #pragma unroll
    for (int r = 0; r < 16; ++r) {
        int ci = r*8 + (tid >> 5), xp = tid & 31;
        tile[ci][xp] = x[(((size_t)b*CINC + ci)*HH + y)*WW + x0 + xp];
    }
    __syncthreads();
    int ci = tid & 127;
    float s = 0.f;
    #pragma unroll
    for (int r = 0; r < 16; ++r) {
        int xp = r*2 + (tid >> 7);
        float v = tile[ci][xp];
        s += v;
        __nv_bfloat16 hi = __float2bfloat16(v);
        __nv_bfloat16 lo = __float2bfloat16(v - __bfloat162float(hi));
        size_t off = (((size_t)b*HP + (y+1))*HP + (x0 + xp + 1))*CINC + ci;
        g_xh[off] = hi;
        g_xl[off] = lo;
    }
    s_red[tid] = s;
    __syncthreads();
    if (tid < 128)
        g_part[((size_t)b*CINC + tid)*128 + y*2 + blockIdx.x] = s_red[tid] + s_red[tid + 128];
}

// ---------------- Kernel 3: attention MLP + softmax + agg bias ----------------
__global__ void __launch_bounds__(128) att_kernel(const float* __restrict__ fc1_w,
                                                  const float* __restrict__ fc2_w,
                                                  const float* __restrict__ fc2_b,
                                                  const float* __restrict__ bias) {
    const int b = blockIdx.x;
    const int tid = threadIdx.x, wid = tid >> 5, lane = tid & 31;
    __shared__ float s_ctx[CINC];
    __shared__ float s_hid[HIDN];
    __shared__ float s_att[NK];

    {
        const float* pp = g_part + ((size_t)b*CINC + tid)*128;
        float s = 0.f;
        #pragma unroll 8
        for (int j = 0; j < 128; ++j) s += pp[j];
        s_ctx[tid] = s * (1.0f / (HH*WW));
    }
    __syncthreads();

    #pragma unroll
    for (int i = 0; i < 8; ++i) {
        int h = wid*8 + i;
        float s = 0.f;
        #pragma unroll
        for (int j = 0; j < 4; ++j) {
            int c = lane + j*32;
            s += s_ctx[c] * fc1_w[h*CINC + c];
        }
        #pragma unroll
        for (int o = 16; o > 0; o >>= 1) s += __shfl_xor_sync(0xffffffffu, s, o);
        if (lane == 0) s_hid[h] = fmaxf(s, 0.f);
    }
    __syncthreads();

    if (wid == 0) {
        int k = lane >> 3, l8 = lane & 7;
        float s = 0.f;
        #pragma unroll
        for (int j = 0; j < 4; ++j) {
            int h = l8 + j*8;
            s += s_hid[h] * fc2_w[k*HIDN + h];
        }
        #pragma unroll
        for (int o = 4; o > 0; o >>= 1) s += __shfl_xor_sync(0xffffffffu, s, o);
        s += fc2_b[k];
        float lg = s * (1.0f / TEMPF);
        float m = lg;
        #pragma unroll
        for (int o = 16; o >= 8; o >>= 1) m = fmaxf(m, __shfl_xor_sync(0xffffffffu, m, o));
        float e = expf(lg - m);
        float sum = e;
        #pragma unroll
        for (int o = 16; o >= 8; o >>= 1) sum += __shfl_xor_sync(0xffffffffu, sum, o);
        if (l8 == 0) {
            float a = e / sum;
            s_att[k] = a;
            g_att[b*NK + k] = a;
        }
    }
    __syncthreads();

    float sb = 0.f;
    #pragma unroll
    for (int k = 0; k < NK; ++k) sb += s_att[k] * bias[k*COUTC + tid];
    g_aggb[b*COUTC + tid] = sb;
}

// ---------------- Kernel 4: aggregate + split weights ----------------
__global__ void __launch_bounds__(256) prepw_kernel(const float* __restrict__ weight) {
    int co = blockIdx.x, b = blockIdx.y;
    float a[NK];
    #pragma unroll
    for (int k = 0; k < NK; ++k) a[k] = g_att[b*NK + k];
    for (int idx = threadIdx.x; idx < 9*CINC; idx += 256) {
        int t = idx >> 7, ci = idx & 127;
        float s = 0.f;
        #pragma unroll
        for (int k = 0; k < NK; ++k)
            s += a[k] * weight[((size_t)(k*COUTC + co)*CINC + ci)*9 + t];
        __nv_bfloat16 hi = __float2bfloat16(s);
        __nv_bfloat16 lo = __float2bfloat16(s - __bfloat162float(hi));
        size_t off = (((size_t)(b*9 + t)*COUTC) + co)*CINC + ci;
        g_wh[off] = hi;
        g_wl[off] = lo;
    }
}

// ---------------- Kernel 5: HMMA conv GEMM, A-resident, 2 CTAs/SM ----------------
// A: padded window 4 rows x 66 cols x 64ci x {hi,lo} = 67584 B, single buffer,
//    reloaded once at the ci-half switch (pipelined behind B).
// B: K=32 sub-stages, row = co: [hi 64B | lo 64B] = 128B, 16KB/stage, x2 buffers.
#define A_LINES 264
#define A_SP    (A_LINES*128)          // 33792 per split
#define A_BUF   (2*A_SP)               // 67584
#define B_SUB   16384
#define B_OFF   A_BUF                  // 67584
#define SMEM_TOTAL (B_OFF + 2*B_SUB)   // 100352

__global__ void __launch_bounds__(256, 2) conv_kernel(float* __restrict__ out) {
    extern __shared__ __align__(1024) char smem[];
    const uint32_t sbase = smem_u32(smem);
    const int tid = threadIdx.x, wid = tid >> 5, lane = tid & 31;
    const int b = blockIdx.y;
    const int y0 = blockIdx.x * 2;

    const int warp_m = wid >> 1;
    const int warp_n = wid & 1;

    const int quad = lane >> 3, l7 = lane & 7;
    const int a_row_off = ((quad & 1) << 3) + l7;
    const int a_k_off   = (quad >> 1) << 4;
    const int b_row_off = ((quad >> 1) << 3) + l7;
    const int b_k_off   = (quad & 1) << 4;

    float acc[2][8][4];
    #pragma unroll
    for (int mi = 0; mi < 2; ++mi)
        #pragma unroll
        for (int nf = 0; nf < 8; ++nf)
            #pragma unroll
            for (int e = 0; e < 4; ++e) acc[mi][nf][e] = 0.f;

    // stage A window for ci-half c2 (4224 cp16)
    auto issue_A = [&](int c2) {
        for (int idx = tid; idx < 2*A_LINES*8; idx += 256) {
            int sp   = idx >= A_LINES*8;
            int rem  = idx - sp*(A_LINES*8);
            int line = rem >> 3;
            int c8   = rem & 7;
            int r4   = line / 66;
            int c66  = line - r4*66;
            size_t e = (((size_t)b*HP + y0 + r4)*HP + c66)*CINC + c2*64;
            const char* src = (const char*)(sp ? g_xl : g_xh) + e*2 + c8*16;
            uint32_t dst = sbase + sp*A_SP + line*128 + ((c8*16) ^ ((line & 7) << 4));
            cp16(dst, src);
        }
    };
    // stage B sub-tile (1024 cp16): row=co, [hi 64B | lo 64B]
    auto issue_B = [&](int bbuf, int g2) {
        const int c2 = g2 / 18, rem = g2 % 18;
        const int tap = rem >> 1, ksub = rem & 1;
        #pragma unroll
        for (int i = 0; i < 4; ++i) {
            int idx = tid + i*256;
            int r  = idx >> 3;
            int c8 = idx & 7;
            int sp = c8 >> 2, c4 = c8 & 3;
            size_t e = (((size_t)(b*9 + tap))*COUTC + r)*CINC + c2*64 + ksub*32;
            const char* src = (const char*)(sp ? g_wl : g_wh) + e*2 + c4*16;
            uint32_t dst = sbase + B_OFF + bbuf*B_SUB + SW128(r*128 + sp*64 + c4*16);
            cp16(dst, src);
        }
    };

    issue_A(0);
    CP_COMMIT();
    issue_B(0, 0);
    CP_COMMIT();

    for (int g2 = 0; g2 < 36; ++g2) {
        __syncthreads();                        // prior compute done before overwrite
        if (g2 == 18) { issue_A(1); CP_COMMIT(); }   // half switch: reload A
        if (g2 + 1 < 36) {
            issue_B((g2 + 1) & 1, g2 + 1);
            CP_COMMIT();
            CP_WAIT1();
        } else {
            CP_WAIT0();
        }
        __syncthreads();

        const int rem = g2 % 18;
        const int tap = rem >> 1, ksub = rem & 1;
        const int dy = tap / 3, dx = tap % 3;
        const uint32_t b_base = sbase + B_OFF + (g2 & 1) * B_SUB;

        #pragma unroll
        for (int kc = 0; kc < 2; ++kc) {
            const int a_kb = ksub*64 + kc*32;   // byte offset in A row
            const int b_kb = kc*32;             // byte offset within hi half of B row
            uint32_t Ah[2][4], Al[2][4], Bh[4][4], Bl[4][4];
            #pragma unroll
            for (int mi = 0; mi < 2; ++mi) {
                int p = warp_m*32 + mi*16 + a_row_off;
                int line = ((p >> 6) + dy)*66 + (p & 63) + dx;
                uint32_t off = line*128 + ((a_kb + a_k_off) ^ ((line & 7) << 4));
                ldmx4(Ah[mi], sbase + off);
                ldmx4(Al[mi], sbase + A_SP + off);
            }
            #pragma unroll
            for (int nj = 0; nj < 4; ++nj) {
                int row = warp_n*64 + nj*16 + b_row_off;
                ldmx4(Bh[nj], b_base + SW128(row*128 + b_kb + b_k_off));
                ldmx4(Bl[nj], b_base + SW128(row*128 + 64 + b_kb + b_k_off));
            }
            #pragma unroll
            for (int mi = 0; mi < 2; ++mi)
                #pragma unroll
                for (int nf = 0; nf < 8; ++nf) {
                    const uint32_t* bh = &Bh[nf >> 1][(nf & 1) * 2];
                    const uint32_t* bl = &Bl[nf >> 1][(nf & 1) * 2];
                    mma_bf16(acc[mi][nf], Ah[mi], bh);   // hh
                    mma_bf16(acc[mi][nf], Al[mi], bh);   // lh
                    mma_bf16(acc[mi][nf], Ah[mi], bl);   // hl
                }
        }
    }

    // ---- epilogue: regs -> smem [co][p] -> coalesced gmem + bias (overlays A)
    __syncthreads();
    float* stage = (float*)smem;            // [128][132] = 67584 B
    #pragma unroll
    for (int mi = 0; mi < 2; ++mi)
        #pragma unroll
        for (int nf = 0; nf < 8; ++nf)
            #pragma unroll
            for (int e = 0; e < 4; ++e) {
                int p  = warp_m*32 + mi*16 + (lane >> 2) + ((e >> 1) << 3);
                int co = warp_n*64 + nf*8 + ((lane & 3) << 1) + (e & 1);
                stage[co*132 + p] = acc[mi][nf][e];
            }
    __syncthreads();
    #pragma unroll
    for (int i = 0; i < 16; ++i) {
        int idx = tid + i*256;               // 4096 quads
        int co = idx >> 5, pq = idx & 31;
        int p = pq * 4;
        float bb = g_aggb[b*COUTC + co];
        const float* sp = stage + co*132 + p;
        float4 v;
        v.x = sp[0] + bb; v.y = sp[1] + bb; v.z = sp[2] + bb; v.w = sp[3] + bb;
        *(float4*)(out + (((size_t)b*COUTC + co)*HH + y0 + (p >> 6))*WW + (p & 63)) = v;
    }
}

extern "C" void kernel_launch(void* const* d_in, const int* in_sizes, int n_in,
                              void* d_out, int out_size) {
    const float* x      = (const float*)d_in[0];
    const float* fc1_w  = (const float*)d_in[1];
    const float* fc2_w  = (const float*)d_in[2];
    const float* fc2_b  = (const float*)d_in[3];
    const float* weight = (const float*)d_in[4];
    const float* bias   = (const float*)d_in[5];
    float* out = (float*)d_out;

    cudaFuncSetAttribute(conv_kernel,
                         cudaFuncAttributeMaxDynamicSharedMemorySize, SMEM_TOTAL);

    halo_kernel<<<dim3(HP, BB), 256>>>();
    prepx_kernel<<<dim3(2, HH, BB), 256>>>(x);
    att_kernel<<<BB, 128>>>(fc1_w, fc2_w, fc2_b, bias);
    prepw_kernel<<<dim3(COUTC, BB), 256>>>(weight);
    conv_kernel<<<dim3(HH/2, BB), 256, SMEM_TOTAL>>>(out);
}

// round 11
// speedup vs baseline: 1.6296x; 1.4181x over previous
#include <cuda_runtime.h>
#include <cuda_fp16.h>
#include <math.h>
#include <stdint.h>

#define BB    32
#define CINC  128
#define HH    64
#define WW    64
#define COUTC 128
#define NK    4
#define HIDN  32
#define TEMPF 34.0f

// halo-padded channel-last input: [B][66][66][CIN] fp16 (hi and lo split)
#define HP 66
__device__ __half g_xh[(size_t)BB*HP*HP*CINC];
__device__ __half g_xl[(size_t)BB*HP*HP*CINC];
// aggregated weights: [B][9][COUT][CIN] fp16 (single precision term)
__device__ __half g_w[(size_t)BB*9*COUTC*CINC];
__device__ float g_part[(size_t)BB*CINC*128];   // mean partials: [b][ci][y*2+xhalf]
__device__ float g_att[BB*NK];
__device__ float g_aggb[BB*COUTC];

// ---------------- PTX helpers ----------------
__device__ __forceinline__ uint32_t smem_u32(const void* p) {
    uint32_t a;
    asm("{ .reg .u64 t; cvta.to.shared.u64 t, %1; cvt.u32.u64 %0, t; }" : "=r"(a) : "l"(p));
    return a;
}
#define SW128(off) ((off) ^ (((off) >> 3) & 0x70))

__device__ __forceinline__ void cp16(uint32_t dst, const void* src) {
    asm volatile("cp.async.cg.shared.global [%0], [%1], 16;" :: "r"(dst), "l"(src));
}
#define CP_COMMIT() asm volatile("cp.async.commit_group;" ::: "memory")
#define CP_WAIT1()  asm volatile("cp.async.wait_group 1;" ::: "memory")
#define CP_WAIT0()  asm volatile("cp.async.wait_group 0;" ::: "memory")

__device__ __forceinline__ void ldmx4(uint32_t* r, uint32_t addr) {
    asm volatile("ldmatrix.sync.aligned.m8n8.x4.shared.b16 {%0,%1,%2,%3}, [%4];"
                 : "=r"(r[0]), "=r"(r[1]), "=r"(r[2]), "=r"(r[3]) : "r"(addr));
}
__device__ __forceinline__ void mma_f16(float* d, const uint32_t* a, const uint32_t* b) {
    asm volatile("mma.sync.aligned.m16n8k16.row.col.f32.f16.f16.f32 "
                 "{%0,%1,%2,%3}, {%4,%5,%6,%7}, {%8,%9}, {%0,%1,%2,%3};"
                 : "+f"(d[0]), "+f"(d[1]), "+f"(d[2]), "+f"(d[3])
                 : "r"(a[0]), "r"(a[1]), "r"(a[2]), "r"(a[3]), "r"(b[0]), "r"(b[1]));
}

// ---------------- Kernel 1: zero halo borders ----------------
__global__ void halo_kernel() {
    int b = blockIdx.y, yy = blockIdx.x;
    bool full = (yy == 0 || yy == HP-1);
    int nsite = full ? HP : 2;
    for (int i = threadIdx.x; i < nsite*CINC; i += 256) {
        int si = i >> 7, ci = i & 127;
        int xx = full ? si : (si ? HP-1 : 0);
        size_t off = (((size_t)b*HP + yy)*HP + xx)*CINC + ci;
        g_xh[off] = __float2half(0.f);
        g_xl[off] = __float2half(0.f);
    }
}

// ---------------- Kernel 2: transpose+split x (fp16), fused mean partials ----------------
__global__ void __launch_bounds__(256) prepx_kernel(const float* __restrict__ x) {
    __shared__ float tile[CINC][33];
    __shared__ float s_red[256];
    int x0 = blockIdx.x * 32, y = blockIdx.y, b = blockIdx.z;
    int tid = threadIdx.x;
    #pragma unroll
    for (int r = 0; r < 16; ++r) {
        int ci = r*8 + (tid >> 5), xp = tid & 31;
        tile[ci][xp] = x[(((size_t)b*CINC + ci)*HH + y)*WW + x0 + xp];
    }
    __syncthreads();
    int ci = tid & 127;
    float s = 0.f;
    #pragma unroll
    for (int r = 0; r < 16; ++r) {
        int xp = r*2 + (tid >> 7);
        float v = tile[ci][xp];
        s += v;
        __half hi = __float2half(v);
        __half lo = __float2half(v - __half2float(hi));
        size_t off = (((size_t)b*HP + (y+1))*HP + (x0 + xp + 1))*CINC + ci;
        g_xh[off] = hi;
        g_xl[off] = lo;
    }
    s_red[tid] = s;
    __syncthreads();
    if (tid < 128)
        g_part[((size_t)b*CINC + tid)*128 + y*2 + blockIdx.x] = s_red[tid] + s_red[tid + 128];
}

// ---------------- Kernel 3: attention MLP + softmax + agg bias ----------------
__global__ void __launch_bounds__(128) att_kernel(const float* __restrict__ fc1_w,
                                                  const float* __restrict__ fc2_w,
                                                  const float* __restrict__ fc2_b,
                                                  const float* __restrict__ bias) {
    const int b = blockIdx.x;
    const int tid = threadIdx.x, wid = tid >> 5, lane = tid & 31;
    __shared__ float s_ctx[CINC];
    __shared__ float s_hid[HIDN];
    __shared__ float s_att[NK];

    {
        const float* pp = g_part + ((size_t)b*CINC + tid)*128;
        float s = 0.f;
        #pragma unroll 8
        for (int j = 0; j < 128; ++j) s += pp[j];
        s_ctx[tid] = s * (1.0f / (HH*WW));
    }
    __syncthreads();

    #pragma unroll
    for (int i = 0; i < 8; ++i) {
        int h = wid*8 + i;
        float s = 0.f;
        #pragma unroll
        for (int j = 0; j < 4; ++j) {
            int c = lane + j*32;
            s += s_ctx[c] * fc1_w[h*CINC + c];
        }
        #pragma unroll
        for (int o = 16; o > 0; o >>= 1) s += __shfl_xor_sync(0xffffffffu, s, o);
        if (lane == 0) s_hid[h] = fmaxf(s, 0.f);
    }
    __syncthreads();

    if (wid == 0) {
        int k = lane >> 3, l8 = lane & 7;
        float s = 0.f;
        #pragma unroll
        for (int j = 0; j < 4; ++j) {
            int h = l8 + j*8;
            s += s_hid[h] * fc2_w[k*HIDN + h];
        }
        #pragma unroll
        for (int o = 4; o > 0; o >>= 1) s += __shfl_xor_sync(0xffffffffu, s, o);
        s += fc2_b[k];
        float lg = s * (1.0f / TEMPF);
        float m = lg;
        #pragma unroll
        for (int o = 16; o >= 8; o >>= 1) m = fmaxf(m, __shfl_xor_sync(0xffffffffu, m, o));
        float e = expf(lg - m);
        float sum = e;
        #pragma unroll
        for (int o = 16; o >= 8; o >>= 1) sum += __shfl_xor_sync(0xffffffffu, sum, o);
        if (l8 == 0) {
            float a = e / sum;
            s_att[k] = a;
            g_att[b*NK + k] = a;
        }
    }
    __syncthreads();

    float sb = 0.f;
    #pragma unroll
    for (int k = 0; k < NK; ++k) sb += s_att[k] * bias[k*COUTC + tid];
    g_aggb[b*COUTC + tid] = sb;
}

// ---------------- Kernel 4: aggregate weights -> fp16 ----------------
__global__ void __launch_bounds__(256) prepw_kernel(const float* __restrict__ weight) {
    int co = blockIdx.x, b = blockIdx.y;
    float a[NK];
    #pragma unroll
    for (int k = 0; k < NK; ++k) a[k] = g_att[b*NK + k];
    for (int idx = threadIdx.x; idx < 9*CINC; idx += 256) {
        int t = idx >> 7, ci = idx & 127;
        float s = 0.f;
        #pragma unroll
        for (int k = 0; k < NK; ++k)
            s += a[k] * weight[((size_t)(k*COUTC + co)*CINC + ci)*9 + t];
        size_t off = (((size_t)(b*9 + t)*COUTC) + co)*CINC + ci;
        g_w[off] = __float2half(s);
    }
}

// ---------------- Kernel 5: HMMA fp16 2-product conv GEMM, A-resident, 2 CTAs/SM ----------------
// A: padded window 4 rows x 66 cols x 64ci x {hi,lo} = 67584 B, single buffer,
//    reloaded once at the ci-half switch (pipelined behind B).
// B: single fp16 term; stage = (tap, ci-half): 128co x 64ci x 2B = 16KB, x2 buffers.
// 18 stages of K=64.
#define A_LINES 264
#define A_SP    (A_LINES*128)          // 33792 per split
#define A_BUF   (2*A_SP)               // 67584
#define B_SUB   16384
#define B_OFF   A_BUF                  // 67584
#define SMEM_TOTAL (B_OFF + 2*B_SUB)   // 100352

__global__ void __launch_bounds__(256, 2) conv_kernel(float* __restrict__ out) {
    extern __shared__ __align__(1024) char smem[];
    const uint32_t sbase = smem_u32(smem);
    const int tid = threadIdx.x, wid = tid >> 5, lane = tid & 31;
    const int b = blockIdx.y;
    const int y0 = blockIdx.x * 2;

    const int warp_m = wid >> 1;
    const int warp_n = wid & 1;

    const int quad = lane >> 3, l7 = lane & 7;
    const int a_row_off = ((quad & 1) << 3) + l7;
    const int a_k_off   = (quad >> 1) << 4;
    const int b_row_off = ((quad >> 1) << 3) + l7;
    const int b_k_off   = (quad & 1) << 4;

    float acc[2][8][4];
    #pragma unroll
    for (int mi = 0; mi < 2; ++mi)
        #pragma unroll
        for (int nf = 0; nf < 8; ++nf)
            #pragma unroll
            for (int e = 0; e < 4; ++e) acc[mi][nf][e] = 0.f;

    // stage A window for ci-half c2 (4224 cp16)
    auto issue_A = [&](int c2) {
        for (int idx = tid; idx < 2*A_LINES*8; idx += 256) {
            int sp   = idx >= A_LINES*8;
            int rem  = idx - sp*(A_LINES*8);
            int line = rem >> 3;
            int c8   = rem & 7;
            int r4   = line / 66;
            int c66  = line - r4*66;
            size_t e = (((size_t)b*HP + y0 + r4)*HP + c66)*CINC + c2*64;
            const char* src = (const char*)(sp ? g_xl : g_xh) + e*2 + c8*16;
            uint32_t dst = sbase + sp*A_SP + line*128 + ((c8*16) ^ ((line & 7) << 4));
            cp16(dst, src);
        }
    };
    // stage B tile (1024 cp16): row = co, 128B = 64 ci fp16
    auto issue_B = [&](int bbuf, int g) {
        const int tap = g % 9, c2 = g / 9;
        #pragma unroll
        for (int i = 0; i < 4; ++i) {
            int idx = tid + i*256;
            int r  = idx >> 3;
            int c8 = idx & 7;
            size_t e = (((size_t)(b*9 + tap))*COUTC + r)*CINC + c2*64;
            const char* src = (const char*)g_w + e*2 + c8*16;
            uint32_t dst = sbase + B_OFF + bbuf*B_SUB + SW128(r*128 + c8*16);
            cp16(dst, src);
        }
    };

    issue_A(0);
    CP_COMMIT();
    issue_B(0, 0);
    CP_COMMIT();

    for (int g = 0; g < 18; ++g) {
        __syncthreads();                        // prior compute done before overwrite
        if (g == 9) { issue_A(1); CP_COMMIT(); }     // ci-half switch: reload A
        if (g + 1 < 18) {
            issue_B((g + 1) & 1, g + 1);
            CP_COMMIT();
            CP_WAIT1();
        } else {
            CP_WAIT0();
        }
        __syncthreads();

        const int tap = g % 9;
        const int dy = tap / 3, dx = tap % 3;
        const uint32_t b_base = sbase + B_OFF + (g & 1) * B_SUB;

        #pragma unroll
        for (int kc = 0; kc < 4; ++kc) {
            const int kb = kc * 32;
            uint32_t Ah[2][4], Al[2][4], Bm[4][4];
            #pragma unroll
            for (int mi = 0; mi < 2; ++mi) {
                int p = warp_m*32 + mi*16 + a_row_off;
                int line = ((p >> 6) + dy)*66 + (p & 63) + dx;
                uint32_t off = line*128 + ((kb + a_k_off) ^ ((line & 7) << 4));
                ldmx4(Ah[mi], sbase + off);
                ldmx4(Al[mi], sbase + A_SP + off);
            }
            #pragma unroll
            for (int nj = 0; nj < 4; ++nj) {
                int row = warp_n*64 + nj*16 + b_row_off;
                ldmx4(Bm[nj], b_base + SW128(row*128 + kb + b_k_off));
            }
            #pragma unroll
            for (int mi = 0; mi < 2; ++mi)
                #pragma unroll
                for (int nf = 0; nf < 8; ++nf) {
                    const uint32_t* bm = &Bm[nf >> 1][(nf & 1) * 2];
                    mma_f16(acc[mi][nf], Ah[mi], bm);   // hi product
                    mma_f16(acc[mi][nf], Al[mi], bm);   // lo product
                }
        }
    }

    // ---- epilogue: regs -> smem [co][p] -> coalesced gmem + bias (overlays A)
    __syncthreads();
    float* stage = (float*)smem;            // [128][132] = 67584 B
    #pragma unroll
    for (int mi = 0; mi < 2; ++mi)
        #pragma unroll
        for (int nf = 0; nf < 8; ++nf)
            #pragma unroll
            for (int e = 0; e < 4; ++e) {
                int p  = warp_m*32 + mi*16 + (lane >> 2) + ((e >> 1) << 3);
                int co = warp_n*64 + nf*8 + ((lane & 3) << 1) + (e & 1);
                stage[co*132 + p] = acc[mi][nf][e];
            }
    __syncthreads();
    #pragma unroll
    for (int i = 0; i < 16; ++i) {
        int idx = tid + i*256;               // 4096 quads
        int co = idx >> 5, pq = idx & 31;
        int p = pq * 4;
        float bb = g_aggb[b*COUTC + co];
        const float* sp = stage + co*132 + p;
        float4 v;
        v.x = sp[0] + bb; v.y = sp[1] + bb; v.z = sp[2] + bb; v.w = sp[3] + bb;
        *(float4*)(out + (((size_t)b*COUTC + co)*HH + y0 + (p >> 6))*WW + (p & 63)) = v;
    }
}

extern "C" void kernel_launch(void* const* d_in, const int* in_sizes, int n_in,
                              void* d_out, int out_size) {
    const float* x      = (const float*)d_in[0];
    const float* fc1_w  = (const float*)d_in[1];
    const float* fc2_w  = (const float*)d_in[2];
    const float* fc2_b  = (const float*)d_in[3];
    const float* weight = (const float*)d_in[4];
    const float* bias   = (const float*)d_in[5];
    float* out = (float*)d_out;

    cudaFuncSetAttribute(conv_kernel,
                         cudaFuncAttributeMaxDynamicSharedMemorySize, SMEM_TOTAL);

    halo_kernel<<<dim3(HP, BB), 256>>>();
    prepx_kernel<<<dim3(2, HH, BB), 256>>>(x);
    att_kernel<<<BB, 128>>>(fc1_w, fc2_w, fc2_b, bias);
    prepw_kernel<<<dim3(COUTC, BB), 256>>>(weight);
    conv_kernel<<<dim3(HH/2, BB), 256, SMEM_TOTAL>>>(out);
}

// round 13
// speedup vs baseline: 2.3808x; 1.4610x over previous
#include <cuda_runtime.h>
#include <cuda_fp16.h>
#include <math.h>
#include <stdint.h>

#define BB    32
#define CINC  128
#define HH    64
#define WW    64
#define COUTC 128
#define NK    4
#define HIDN  32
#define TEMPF 34.0f

// halo-padded channel-last input: [B][66][66][CIN] fp16
#define HP 66
__device__ __half g_x[(size_t)BB*HP*HP*CINC];
// aggregated weights: [B][9][COUT][CIN] fp16
__device__ __half g_w[(size_t)BB*9*COUTC*CINC];
__device__ float g_part[(size_t)BB*CINC*128];   // mean partials: [b][ci][y*2+xhalf]
__device__ float g_att[BB*NK];
__device__ float g_aggb[BB*COUTC];

// ---------------- PTX helpers ----------------
__device__ __forceinline__ uint32_t smem_u32(const void* p) {
    uint32_t a;
    asm("{ .reg .u64 t; cvta.to.shared.u64 t, %1; cvt.u32.u64 %0, t; }" : "=r"(a) : "l"(p));
    return a;
}
#define SW128(off) ((off) ^ (((off) >> 3) & 0x70))

__device__ __forceinline__ void cp16(uint32_t dst, const void* src) {
    asm volatile("cp.async.cg.shared.global [%0], [%1], 16;" :: "r"(dst), "l"(src));
}
#define CP_COMMIT() asm volatile("cp.async.commit_group;" ::: "memory")
#define CP_WAIT1()  asm volatile("cp.async.wait_group 1;" ::: "memory")
#define CP_WAIT0()  asm volatile("cp.async.wait_group 0;" ::: "memory")

__device__ __forceinline__ void ldmx4(uint32_t* r, uint32_t addr) {
    asm volatile("ldmatrix.sync.aligned.m8n8.x4.shared.b16 {%0,%1,%2,%3}, [%4];"
                 : "=r"(r[0]), "=r"(r[1]), "=r"(r[2]), "=r"(r[3]) : "r"(addr));
}
__device__ __forceinline__ void mma_f16(float* d, const uint32_t* a, const uint32_t* b) {
    asm volatile("mma.sync.aligned.m16n8k16.row.col.f32.f16.f16.f32 "
                 "{%0,%1,%2,%3}, {%4,%5,%6,%7}, {%8,%9}, {%0,%1,%2,%3};"
                 : "+f"(d[0]), "+f"(d[1]), "+f"(d[2]), "+f"(d[3])
                 : "r"(a[0]), "r"(a[1]), "r"(a[2]), "r"(a[3]), "r"(b[0]), "r"(b[1]));
}

// ---------------- Kernel 1: zero halo borders ----------------
__global__ void halo_kernel() {
    int b = blockIdx.y, yy = blockIdx.x;
    bool full = (yy == 0 || yy == HP-1);
    int nsite = full ? HP : 2;
    for (int i = threadIdx.x; i < nsite*CINC; i += 256) {
        int si = i >> 7, ci = i & 127;
        int xx = full ? si : (si ? HP-1 : 0);
        size_t off = (((size_t)b*HP + yy)*HP + xx)*CINC + ci;
        g_x[off] = __float2half(0.f);
    }
}

// ---------------- Kernel 2: transpose x -> fp16, fused mean partials ----------------
__global__ void __launch_bounds__(256) prepx_kernel(const float* __restrict__ x) {
    __shared__ float tile[CINC][33];
    __shared__ float s_red[256];
    int x0 = blockIdx.x * 32, y = blockIdx.y, b = blockIdx.z;
    int tid = threadIdx.x;
    #pragma unroll
    for (int r = 0; r < 16; ++r) {
        int ci = r*8 + (tid >> 5), xp = tid & 31;
        tile[ci][xp] = x[(((size_t)b*CINC + ci)*HH + y)*WW + x0 + xp];
    }
    __syncthreads();
    int ci = tid & 127;
    float s = 0.f;
    #pragma unroll
    for (int r = 0; r < 16; ++r) {
        int xp = r*2 + (tid >> 7);
        float v = tile[ci][xp];
        s += v;
        size_t off = (((size_t)b*HP + (y+1))*HP + (x0 + xp + 1))*CINC + ci;
        g_x[off] = __float2half(v);
    }
    s_red[tid] = s;
    __syncthreads();
    if (tid < 128)
        g_part[((size_t)b*CINC + tid)*128 + y*2 + blockIdx.x] = s_red[tid] + s_red[tid + 128];
}

// ---------------- Kernel 3: attention MLP + softmax + agg bias ----------------
__global__ void __launch_bounds__(128) att_kernel(const float* __restrict__ fc1_w,
                                                  const float* __restrict__ fc2_w,
                                                  const float* __restrict__ fc2_b,
                                                  const float* __restrict__ bias) {
    const int b = blockIdx.x;
    const int tid = threadIdx.x, wid = tid >> 5, lane = tid & 31;
    __shared__ float s_ctx[CINC];
    __shared__ float s_hid[HIDN];
    __shared__ float s_att[NK];

    {
        const float* pp = g_part + ((size_t)b*CINC + tid)*128;
        float s = 0.f;
        #pragma unroll 8
        for (int j = 0; j < 128; ++j) s += pp[j];
        s_ctx[tid] = s * (1.0f / (HH*WW));
    }
    __syncthreads();

    #pragma unroll
    for (int i = 0; i < 8; ++i) {
        int h = wid*8 + i;
        float s = 0.f;
        #pragma unroll
        for (int j = 0; j < 4; ++j) {
            int c = lane + j*32;
            s += s_ctx[c] * fc1_w[h*CINC + c];
        }
        #pragma unroll
        for (int o = 16; o > 0; o >>= 1) s += __shfl_xor_sync(0xffffffffu, s, o);
        if (lane == 0) s_hid[h] = fmaxf(s, 0.f);
    }
    __syncthreads();

    if (wid == 0) {
        int k = lane >> 3, l8 = lane & 7;
        float s = 0.f;
        #pragma unroll
        for (int j = 0; j < 4; ++j) {
            int h = l8 + j*8;
            s += s_hid[h] * fc2_w[k*HIDN + h];
        }
        #pragma unroll
        for (int o = 4; o > 0; o >>= 1) s += __shfl_xor_sync(0xffffffffu, s, o);
        s += fc2_b[k];
        float lg = s * (1.0f / TEMPF);
        float m = lg;
        #pragma unroll
        for (int o = 16; o >= 8; o >>= 1) m = fmaxf(m, __shfl_xor_sync(0xffffffffu, m, o));
        float e = expf(lg - m);
        float sum = e;
        #pragma unroll
        for (int o = 16; o >= 8; o >>= 1) sum += __shfl_xor_sync(0xffffffffu, sum, o);
        if (l8 == 0) {
            float a = e / sum;
            s_att[k] = a;
            g_att[b*NK + k] = a;
        }
    }
    __syncthreads();

    float sb = 0.f;
    #pragma unroll
    for (int k = 0; k < NK; ++k) sb += s_att[k] * bias[k*COUTC + tid];
    g_aggb[b*COUTC + tid] = sb;
}

// ---------------- Kernel 4: aggregate weights -> fp16 ----------------
__global__ void __launch_bounds__(256) prepw_kernel(const float* __restrict__ weight) {
    int co = blockIdx.x, b = blockIdx.y;
    float a[NK];
    #pragma unroll
    for (int k = 0; k < NK; ++k) a[k] = g_att[b*NK + k];
    for (int idx = threadIdx.x; idx < 9*CINC; idx += 256) {
        int t = idx >> 7, ci = idx & 127;
        float s = 0.f;
        #pragma unroll
        for (int k = 0; k < NK; ++k)
            s += a[k] * weight[((size_t)(k*COUTC + co)*CINC + ci)*9 + t];
        size_t off = (((size_t)(b*9 + t)*COUTC) + co)*CINC + ci;
        g_w[off] = __float2half(s);
    }
}

// ---------------- Kernel 5: HMMA fp16 single-product conv GEMM ----------------
// CTA: M=128 pixels (2 rows x 64), N=128 couts. 18 stages of K=64 (tap x ci-half).
// A: padded window 4 rows x 66 cols x 64ci fp16 = 33792 B, single buffer,
//    reloaded once at the ci-half switch (pipelined behind B).
// B: stage = (tap, ci-half): 128co x 64ci x 2B = 16KB, x2 buffers.
// Epilogue stage [128][132] f32 = 67584 B overlays everything.
#define A_LINES 264
#define A_SP    (A_LINES*128)          // 33792
#define B_SUB   16384
#define B_OFF   A_SP                   // 33792
#define SMEM_TOTAL 67584               // max(B_OFF + 2*B_SUB = 66560, epilogue 67584)

__global__ void __launch_bounds__(256, 2) conv_kernel(float* __restrict__ out) {
    extern __shared__ __align__(1024) char smem[];
    const uint32_t sbase = smem_u32(smem);
    const int tid = threadIdx.x, wid = tid >> 5, lane = tid & 31;
    const int b = blockIdx.y;
    const int y0 = blockIdx.x * 2;

    const int warp_m = wid >> 1;
    const int warp_n = wid & 1;

    const int quad = lane >> 3, l7 = lane & 7;
    const int a_row_off = ((quad & 1) << 3) + l7;
    const int a_k_off   = (quad >> 1) << 4;
    const int b_row_off = ((quad >> 1) << 3) + l7;
    const int b_k_off   = (quad & 1) << 4;

    float acc[2][8][4];
    #pragma unroll
    for (int mi = 0; mi < 2; ++mi)
        #pragma unroll
        for (int nf = 0; nf < 8; ++nf)
            #pragma unroll
            for (int e = 0; e < 4; ++e) acc[mi][nf][e] = 0.f;

    // stage A window for ci-half c2 (2112 cp16)
    auto issue_A = [&](int c2) {
        for (int idx = tid; idx < A_LINES*8; idx += 256) {
            int line = idx >> 3;
            int c8   = idx & 7;
            int r4   = line / 66;
            int c66  = line - r4*66;
            size_t e = (((size_t)b*HP + y0 + r4)*HP + c66)*CINC + c2*64;
            const char* src = (const char*)g_x + e*2 + c8*16;
            uint32_t dst = sbase + line*128 + ((c8*16) ^ ((line & 7) << 4));
            cp16(dst, src);
        }
    };
    // stage B tile (1024 cp16): row = co, 128B = 64 ci fp16
    auto issue_B = [&](int bbuf, int g) {
        const int tap = g % 9, c2 = g / 9;
        #pragma unroll
        for (int i = 0; i < 4; ++i) {
            int idx = tid + i*256;
            int r  = idx >> 3;
            int c8 = idx & 7;
            size_t e = (((size_t)(b*9 + tap))*COUTC + r)*CINC + c2*64;
            const char* src = (const char*)g_w + e*2 + c8*16;
            uint32_t dst = sbase + B_OFF + bbuf*B_SUB + SW128(r*128 + c8*16);
            cp16(dst, src);
        }
    };

    issue_A(0);
    CP_COMMIT();
    issue_B(0, 0);
    CP_COMMIT();

    for (int g = 0; g < 18; ++g) {
        __syncthreads();                        // prior compute done before overwrite
        if (g == 9) { issue_A(1); CP_COMMIT(); }     // ci-half switch: reload A
        if (g + 1 < 18) {
            issue_B((g + 1) & 1, g + 1);
            CP_COMMIT();
            CP_WAIT1();
        } else {
            CP_WAIT0();
        }
        __syncthreads();

        const int tap = g % 9;
        const int dy = tap / 3, dx = tap % 3;
        const uint32_t b_base = sbase + B_OFF + (g & 1) * B_SUB;

        #pragma unroll
        for (int kc = 0; kc < 4; ++kc) {
            const int kb = kc * 32;
            uint32_t Am[2][4], Bm[4][4];
            #pragma unroll
            for (int mi = 0; mi < 2; ++mi) {
                int p = warp_m*32 + mi*16 + a_row_off;
                int line = ((p >> 6) + dy)*66 + (p & 63) + dx;
                uint32_t off = line*128 + ((kb + a_k_off) ^ ((line & 7) << 4));
                ldmx4(Am[mi], sbase + off);
            }
            #pragma unroll
            for (int nj = 0; nj < 4; ++nj) {
                int row = warp_n*64 + nj*16 + b_row_off;
                ldmx4(Bm[nj], b_base + SW128(row*128 + kb + b_k_off));
            }
            #pragma unroll
            for (int mi = 0; mi < 2; ++mi)
                #pragma unroll
                for (int nf = 0; nf < 8; ++nf) {
                    const uint32_t* bm = &Bm[nf >> 1][(nf & 1) * 2];
                    mma_f16(acc[mi][nf], Am[mi], bm);
                }
        }
    }

    // ---- epilogue: regs -> smem [co][p] -> coalesced gmem + bias
    __syncthreads();
    float* stage = (float*)smem;            // [128][132] = 67584 B
    #pragma unroll
    for (int mi = 0; mi < 2; ++mi)
        #pragma unroll
        for (int nf = 0; nf < 8; ++nf)
            #pragma unroll
            for (int e = 0; e < 4; ++e) {
                int p  = warp_m*32 + mi*16 + (lane >> 2) + ((e >> 1) << 3);
                int co = warp_n*64 + nf*8 + ((lane & 3) << 1) + (e & 1);
                stage[co*132 + p] = acc[mi][nf][e];
            }
    __syncthreads();
    #pragma unroll
    for (int i = 0; i < 16; ++i) {
        int idx = tid + i*256;               // 4096 quads
        int co = idx >> 5, pq = idx & 31;
        int p = pq * 4;
        float bb = g_aggb[b*COUTC + co];
        const float* sp = stage + co*132 + p;
        float4 v;
        v.x = sp[0] + bb; v.y = sp[1] + bb; v.z = sp[2] + bb; v.w = sp[3] + bb;
        *(float4*)(out + (((size_t)b*COUTC + co)*HH + y0 + (p >> 6))*WW + (p & 63)) = v;
    }
}

extern "C" void kernel_launch(void* const* d_in, const int* in_sizes, int n_in,
                              void* d_out, int out_size) {
    const float* x      = (const float*)d_in[0];
    const float* fc1_w  = (const float*)d_in[1];
    const float* fc2_w  = (const float*)d_in[2];
    const float* fc2_b  = (const float*)d_in[3];
    const float* weight = (const float*)d_in[4];
    const float* bias   = (const float*)d_in[5];
    float* out = (float*)d_out;

    cudaFuncSetAttribute(conv_kernel,
                         cudaFuncAttributeMaxDynamicSharedMemorySize, SMEM_TOTAL);

    halo_kernel<<<dim3(HP, BB), 256>>>();
    prepx_kernel<<<dim3(2, HH, BB), 256>>>(x);
    att_kernel<<<BB, 128>>>(fc1_w, fc2_w, fc2_b, bias);
    prepw_kernel<<<dim3(COUTC, BB), 256>>>(weight);
    conv_kernel<<<dim3(HH/2, BB), 256, SMEM_TOTAL>>>(out);
}